// round 8
// baseline (speedup 1.0000x reference)
#include <cuda_runtime.h>

#define NB 256
#define NT 1024
#define NV 5000
#define ND 100
#define NH 64
#define NC 2

// Scratch: EW = E @ W + b, [V, H]. 1.28 MB -> fully L2-resident.
__device__ float g_EWb[NV * NH];

// ---------------------------------------------------------------------------
// Kernel A: EWb[v][j] = sum_d E[v][d] * W[d][j] + b[j]
// ---------------------------------------------------------------------------
__global__ void ew_kernel(const float* __restrict__ E,
                          const float* __restrict__ W,
                          const float* __restrict__ bias) {
    int v = blockIdx.x * 4 + (threadIdx.x >> 6);
    int j = threadIdx.x & 63;
    if (v >= NV) return;
    float acc = bias[j];
    const float* e = E + v * ND;
    #pragma unroll 4
    for (int d = 0; d < ND; d++)
        acc = fmaf(e[d], W[d * NH + j], acc);
    g_EWb[v * NH + j] = acc;
}

// HW tanh (MUFU.TANH): lat 16, single instruction, ~2^-11 error.
__device__ __forceinline__ float tanh_fast(float x) {
    float y;
    asm("tanh.approx.f32 %0, %1;" : "=f"(y) : "f"(x));
    return y;
}

// ---------------------------------------------------------------------------
// Kernel B: masked tanh RNN, T=1024 steps + mean-pool + dense + sigmoid.
// TWO ROWS PER BLOCK (128 threads = 4 warps), 128 blocks <= 148 SMs ->
// exactly one block per SM, ONE warp per SMSP, no cross-block contention
// and no wave imbalance (R4's hidden cost: 108 of 148 SMs carried 2 blocks).
// Intra-row decomposition is R4's winner: K-split by 2 in-warp, lanes
// (l, l+16) of warp w own output j = 16w + (l&15), lane's K-half = l>>4,
// 32 scalar FFMA + 8 LDS.128 per row, halves merged by one shfl.bfly(16).
// The two rows share Ucol registers (same U) and one __syncthreads per
// step; their independent serial tails (tree->shfl->tanh->STS) interleave,
// so row B's FMAs fill row A's latency stalls.
// ---------------------------------------------------------------------------
__global__ void __launch_bounds__(128) rnn_kernel(
    const int* __restrict__ tokens,
    const float* __restrict__ U,
    const float* __restrict__ Wd,
    const float* __restrict__ bd,
    float* __restrict__ out)
{
    __shared__ __align__(16) float hbufA[2][NH];
    __shared__ __align__(16) float hbufB[2][NH];
    __shared__ float red[4][4];
    const int w     = threadIdx.x >> 5;
    const int l     = threadIdx.x & 31;
    const int j     = w * 16 + (l & 15);
    const int kbase = (l >> 4) * 32;
    const bool low  = (l < 16);
    const int rA    = blockIdx.x * 2;
    const int rB    = rA + 1;

    // U[kbase..kbase+31][j] in 32 registers — shared by both rows.
    float Ucol[NH / 2];
    #pragma unroll
    for (int k = 0; k < NH / 2; k++)
        Ucol[k] = U[(kbase + k) * NH + j];

    if (threadIdx.x < NH) {
        hbufA[0][threadIdx.x] = 0.f;
        hbufB[0][threadIdx.x] = 0.f;
    }
    __syncthreads();

    const int* trowA = tokens + rA * NT;
    const int* trowB = tokens + rB * NT;
    float hA = 0.f, sA = 0.f, hB = 0.f, sB = 0.f;

    // Pipeline per row: tokens 3 ahead, EW rows 2 ahead (>= L2 ~234cyc).
    int tokA0 = trowA[0], tokA1 = trowA[1], tokA2 = trowA[2];
    int tokB0 = trowB[0], tokB1 = trowB[1], tokB2 = trowB[2];
    float ewA0 = g_EWb[tokA0 * NH + j];
    float ewA1 = g_EWb[tokA1 * NH + j];
    float ewB0 = g_EWb[tokB0 * NH + j];
    float ewB1 = g_EWb[tokB1 * NH + j];

    #pragma unroll 2
    for (int t = 0; t < NT; t++) {
        int t3 = (t + 3 < NT) ? (t + 3) : (NT - 1);
        int tokA3 = trowA[t3];
        int tokB3 = trowB[t3];
        float ewA2 = g_EWb[tokA2 * NH + j];
        float ewB2 = g_EWb[tokB2 * NH + j];

        // ---- Row A partial dot over this lane's K-half ----
        const float4* hpA = reinterpret_cast<const float4*>(hbufA[t & 1] + kbase);
        float4 a0v = hpA[0], a1v = hpA[1], a2v = hpA[2], a3v = hpA[3];
        float4 a4v = hpA[4], a5v = hpA[5], a6v = hpA[6], a7v = hpA[7];
        float x0 = 0.f, x1 = 0.f, x2 = 0.f, x3 = 0.f;
        float x4 = 0.f, x5 = 0.f, x6 = 0.f, x7 = 0.f;
        x0 = fmaf(a0v.x, Ucol[0],  x0);  x1 = fmaf(a0v.y, Ucol[1],  x1);
        x2 = fmaf(a0v.z, Ucol[2],  x2);  x3 = fmaf(a0v.w, Ucol[3],  x3);
        x4 = fmaf(a1v.x, Ucol[4],  x4);  x5 = fmaf(a1v.y, Ucol[5],  x5);
        x6 = fmaf(a1v.z, Ucol[6],  x6);  x7 = fmaf(a1v.w, Ucol[7],  x7);
        x0 = fmaf(a2v.x, Ucol[8],  x0);  x1 = fmaf(a2v.y, Ucol[9],  x1);
        x2 = fmaf(a2v.z, Ucol[10], x2);  x3 = fmaf(a2v.w, Ucol[11], x3);
        x4 = fmaf(a3v.x, Ucol[12], x4);  x5 = fmaf(a3v.y, Ucol[13], x5);
        x6 = fmaf(a3v.z, Ucol[14], x6);  x7 = fmaf(a3v.w, Ucol[15], x7);
        x0 = fmaf(a4v.x, Ucol[16], x0);  x1 = fmaf(a4v.y, Ucol[17], x1);
        x2 = fmaf(a4v.z, Ucol[18], x2);  x3 = fmaf(a4v.w, Ucol[19], x3);
        x4 = fmaf(a5v.x, Ucol[20], x4);  x5 = fmaf(a5v.y, Ucol[21], x5);
        x6 = fmaf(a5v.z, Ucol[22], x6);  x7 = fmaf(a5v.w, Ucol[23], x7);
        x0 = fmaf(a6v.x, Ucol[24], x0);  x1 = fmaf(a6v.y, Ucol[25], x1);
        x2 = fmaf(a6v.z, Ucol[26], x2);  x3 = fmaf(a6v.w, Ucol[27], x3);
        x4 = fmaf(a7v.x, Ucol[28], x4);  x5 = fmaf(a7v.y, Ucol[29], x5);
        x6 = fmaf(a7v.z, Ucol[30], x6);  x7 = fmaf(a7v.w, Ucol[31], x7);
        float pA = ((x0 + x1) + (x2 + x3)) + ((x4 + x5) + (x6 + x7));

        // ---- Row B partial dot (independent chain; ptxas interleaves) ----
        const float4* hpB = reinterpret_cast<const float4*>(hbufB[t & 1] + kbase);
        float4 b0v = hpB[0], b1v = hpB[1], b2v = hpB[2], b3v = hpB[3];
        float4 b4v = hpB[4], b5v = hpB[5], b6v = hpB[6], b7v = hpB[7];
        float y0 = 0.f, y1 = 0.f, y2 = 0.f, y3 = 0.f;
        float y4 = 0.f, y5 = 0.f, y6 = 0.f, y7 = 0.f;
        y0 = fmaf(b0v.x, Ucol[0],  y0);  y1 = fmaf(b0v.y, Ucol[1],  y1);
        y2 = fmaf(b0v.z, Ucol[2],  y2);  y3 = fmaf(b0v.w, Ucol[3],  y3);
        y4 = fmaf(b1v.x, Ucol[4],  y4);  y5 = fmaf(b1v.y, Ucol[5],  y5);
        y6 = fmaf(b1v.z, Ucol[6],  y6);  y7 = fmaf(b1v.w, Ucol[7],  y7);
        y0 = fmaf(b2v.x, Ucol[8],  y0);  y1 = fmaf(b2v.y, Ucol[9],  y1);
        y2 = fmaf(b2v.z, Ucol[10], y2);  y3 = fmaf(b2v.w, Ucol[11], y3);
        y4 = fmaf(b3v.x, Ucol[12], y4);  y5 = fmaf(b3v.y, Ucol[13], y5);
        y6 = fmaf(b3v.z, Ucol[14], y6);  y7 = fmaf(b3v.w, Ucol[15], y7);
        y0 = fmaf(b4v.x, Ucol[16], y0);  y1 = fmaf(b4v.y, Ucol[17], y1);
        y2 = fmaf(b4v.z, Ucol[18], y2);  y3 = fmaf(b4v.w, Ucol[19], y3);
        y4 = fmaf(b5v.x, Ucol[20], y4);  y5 = fmaf(b5v.y, Ucol[21], y5);
        y6 = fmaf(b5v.z, Ucol[22], y6);  y7 = fmaf(b5v.w, Ucol[23], y7);
        y0 = fmaf(b6v.x, Ucol[24], y0);  y1 = fmaf(b6v.y, Ucol[25], y1);
        y2 = fmaf(b6v.z, Ucol[26], y2);  y3 = fmaf(b6v.w, Ucol[27], y3);
        y4 = fmaf(b7v.x, Ucol[28], y4);  y5 = fmaf(b7v.y, Ucol[29], y5);
        y6 = fmaf(b7v.z, Ucol[30], y6);  y7 = fmaf(b7v.w, Ucol[31], y7);
        float pB = ((y0 + y1) + (y2 + y3)) + ((y4 + y5) + (y6 + y7));

        // ---- Merge K-halves + tanh + masked update, both rows ----
        float aA = pA + __shfl_xor_sync(0xffffffffu, pA, 16) + ewA0;
        float aB = pB + __shfl_xor_sync(0xffffffffu, pB, 16) + ewB0;
        float hnA = tanh_fast(aA);
        float hnB = tanh_fast(aB);
        if (tokA0 != 0) hA = hnA;
        if (tokB0 != 0) hB = hnB;
        sA += hA;
        sB += hB;

        if (low) hbufA[(t & 1) ^ 1][j] = hA;
        else     hbufB[(t & 1) ^ 1][j] = hB;   // high lanes publish row B
        __syncthreads();

        tokA0 = tokA1; tokA1 = tokA2; tokA2 = tokA3;
        tokB0 = tokB1; tokB1 = tokB2; tokB2 = tokB3;
        ewA0 = ewA1;  ewA1 = ewA2;
        ewB0 = ewB1;  ewB1 = ewB2;
    }

    // Epilogue: mean pool -> dense (64 -> 2) -> sigmoid, both rows.
    // Each output j is duplicated in 2 lanes; count only l<16.
    float pA_ = sA * (1.0f / NT);
    float pB_ = sB * (1.0f / NT);
    float wd0 = Wd[j * NC + 0], wd1 = Wd[j * NC + 1];
    float cA0 = low ? pA_ * wd0 : 0.f;
    float cA1 = low ? pA_ * wd1 : 0.f;
    float cB0 = low ? pB_ * wd0 : 0.f;
    float cB1 = low ? pB_ * wd1 : 0.f;
    #pragma unroll
    for (int off = 16; off; off >>= 1) {
        cA0 += __shfl_xor_sync(0xffffffffu, cA0, off);
        cA1 += __shfl_xor_sync(0xffffffffu, cA1, off);
        cB0 += __shfl_xor_sync(0xffffffffu, cB0, off);
        cB1 += __shfl_xor_sync(0xffffffffu, cB1, off);
    }
    if (l == 0) {
        red[w][0] = cA0; red[w][1] = cA1;
        red[w][2] = cB0; red[w][3] = cB1;
    }
    __syncthreads();
    if (threadIdx.x == 0) {
        float CA0 = red[0][0] + red[1][0] + red[2][0] + red[3][0] + bd[0];
        float CA1 = red[0][1] + red[1][1] + red[2][1] + red[3][1] + bd[1];
        float CB0 = red[0][2] + red[1][2] + red[2][2] + red[3][2] + bd[0];
        float CB1 = red[0][3] + red[1][3] + red[2][3] + red[3][3] + bd[1];
        out[rA * NC + 0] = 1.0f / (1.0f + expf(-CA0));
        out[rA * NC + 1] = 1.0f / (1.0f + expf(-CA1));
        out[rB * NC + 0] = 1.0f / (1.0f + expf(-CB0));
        out[rB * NC + 1] = 1.0f / (1.0f + expf(-CB1));
    }
}

// ---------------------------------------------------------------------------
extern "C" void kernel_launch(void* const* d_in, const int* in_sizes, int n_in,
                              void* d_out, int out_size) {
    const int*   tokens = (const int*)  d_in[0];
    const float* E      = (const float*)d_in[1];
    const float* W      = (const float*)d_in[2];
    const float* U      = (const float*)d_in[3];
    const float* bias   = (const float*)d_in[4];
    const float* Wd     = (const float*)d_in[5];
    const float* bd     = (const float*)d_in[6];
    float* out = (float*)d_out;

    ew_kernel<<<(NV + 3) / 4, 256>>>(E, W, bias);
    rnn_kernel<<<NB / 2, 128>>>(tokens, U, Wd, bd, out);
}

// round 10
// speedup vs baseline: 1.4221x; 1.4221x over previous
#include <cuda_runtime.h>

#define NB 256
#define NT 1024
#define NV 5000
#define ND 100
#define NH 64
#define NC 2

// Scratch: EW = E @ W + b, [V, H]. 1.28 MB -> fully L2-resident.
__device__ float g_EWb[NV * NH];

// ---------------------------------------------------------------------------
// Kernel A: EWb[v][j] = sum_d E[v][d] * W[d][j] + b[j]
// ---------------------------------------------------------------------------
__global__ void ew_kernel(const float* __restrict__ E,
                          const float* __restrict__ W,
                          const float* __restrict__ bias) {
    int v = blockIdx.x * 4 + (threadIdx.x >> 6);
    int j = threadIdx.x & 63;
    if (v >= NV) return;
    float acc = bias[j];
    const float* e = E + v * ND;
    #pragma unroll 4
    for (int d = 0; d < ND; d++)
        acc = fmaf(e[d], W[d * NH + j], acc);
    g_EWb[v * NH + j] = acc;
}

// HW tanh (MUFU.TANH): lat 16, single instruction, ~2^-11 error.
__device__ __forceinline__ float tanh_fast(float x) {
    float y;
    asm("tanh.approx.f32 %0, %1;" : "=f"(y) : "f"(x));
    return y;
}

// ---------------------------------------------------------------------------
// Kernel B: masked tanh RNN, T=1024 steps + mean-pool + dense + sigmoid.
// STRUCTURE = R4 (best, 166us): one block (128 thr = 4 warps) per row,
// K-split by 2 in-warp, lanes (l, l+16) of warp w own output j = 16w+(l&15),
// 32 scalar FFMA + 8 LDS.128 per thread, ptxas-scheduled unroll-2 ping-pong.
// R9 deltas (step body only):
//  * EARLY SPLIT SHUFFLE: K[0..15] -> a0..a3, K[16..31] -> a4..a7; reduce
//    p1 first and issue its shfl while the second half's FMAs still issue,
//    hiding most of the 26-cyc shfl latency.
//  * ew folded into a0 (low half only; partner lane inherits via merge),
//    removing the tail FADD; the FSEL resolves 2 steps ahead of use.
// ---------------------------------------------------------------------------
__global__ void __launch_bounds__(128) rnn_kernel(
    const int* __restrict__ tokens,
    const float* __restrict__ U,
    const float* __restrict__ Wd,
    const float* __restrict__ bd,
    float* __restrict__ out)
{
    __shared__ __align__(16) float hbuf[2][NH];
    __shared__ float red[4][2];
    const int w     = threadIdx.x >> 5;
    const int l     = threadIdx.x & 31;
    const int j     = w * 16 + (l & 15);
    const int kbase = (l >> 4) * 32;
    const bool low  = (l < 16);
    const int b     = blockIdx.x;

    // U[kbase..kbase+31][j] in 32 registers.
    float Ucol[NH / 2];
    #pragma unroll
    for (int k = 0; k < NH / 2; k++)
        Ucol[k] = U[(kbase + k) * NH + j];

    if (threadIdx.x < NH) hbuf[0][threadIdx.x] = 0.f;
    __syncthreads();

    const int* trow = tokens + b * NT;
    float h = 0.f, s = 0.f;

    // Pipeline: tokens 3 ahead, EW rows 2 ahead (2 steps >= L2 ~234cyc).
    int tok0 = trow[0];
    int tok1 = trow[1];
    int tok2 = trow[2];
    float ew0 = g_EWb[tok0 * NH + j];
    float ew1 = g_EWb[tok1 * NH + j];

    #pragma unroll 2
    for (int t = 0; t < NT; t++) {
        int t3 = (t + 3 < NT) ? (t + 3) : (NT - 1);
        int tok3 = trow[t3];
        float ew2 = g_EWb[tok2 * NH + j];

        const float4* hp = reinterpret_cast<const float4*>(hbuf[t & 1] + kbase);
        float4 h0 = hp[0], h1 = hp[1], h2 = hp[2], h3 = hp[3];
        float4 h4 = hp[4], h5 = hp[5], h6 = hp[6], h7 = hp[7];

        // First K-half-of-half: K[kbase .. kbase+15] -> a0..a3.
        float a0 = low ? ew0 : 0.f;        // ew folded; resolves 2 steps early
        float a1 = 0.f, a2 = 0.f, a3 = 0.f;
        a0 = fmaf(h0.x, Ucol[0],  a0);  a1 = fmaf(h0.y, Ucol[1],  a1);
        a2 = fmaf(h0.z, Ucol[2],  a2);  a3 = fmaf(h0.w, Ucol[3],  a3);
        a0 = fmaf(h1.x, Ucol[4],  a0);  a1 = fmaf(h1.y, Ucol[5],  a1);
        a2 = fmaf(h1.z, Ucol[6],  a2);  a3 = fmaf(h1.w, Ucol[7],  a3);
        a0 = fmaf(h2.x, Ucol[8],  a0);  a1 = fmaf(h2.y, Ucol[9],  a1);
        a2 = fmaf(h2.z, Ucol[10], a2);  a3 = fmaf(h2.w, Ucol[11], a3);
        a0 = fmaf(h3.x, Ucol[12], a0);  a1 = fmaf(h3.y, Ucol[13], a1);
        a2 = fmaf(h3.z, Ucol[14], a2);  a3 = fmaf(h3.w, Ucol[15], a3);
        float p1 = (a0 + a1) + (a2 + a3);
        // Issue the first merge shfl NOW; its 26-cyc latency hides under
        // the second half's FMA issue below.
        float q1 = __shfl_xor_sync(0xffffffffu, p1, 16);

        // Second K-half-of-half: K[kbase+16 .. kbase+31] -> a4..a7.
        float a4 = 0.f, a5 = 0.f, a6 = 0.f, a7 = 0.f;
        a4 = fmaf(h4.x, Ucol[16], a4);  a5 = fmaf(h4.y, Ucol[17], a5);
        a6 = fmaf(h4.z, Ucol[18], a6);  a7 = fmaf(h4.w, Ucol[19], a7);
        a4 = fmaf(h5.x, Ucol[20], a4);  a5 = fmaf(h5.y, Ucol[21], a5);
        a6 = fmaf(h5.z, Ucol[22], a6);  a7 = fmaf(h5.w, Ucol[23], a7);
        a4 = fmaf(h6.x, Ucol[24], a4);  a5 = fmaf(h6.y, Ucol[25], a5);
        a6 = fmaf(h6.z, Ucol[26], a6);  a7 = fmaf(h6.w, Ucol[27], a7);
        a4 = fmaf(h7.x, Ucol[28], a4);  a5 = fmaf(h7.y, Ucol[29], a5);
        a6 = fmaf(h7.z, Ucol[30], a6);  a7 = fmaf(h7.w, Ucol[31], a7);
        float p2 = (a4 + a5) + (a6 + a7);
        float q2 = __shfl_xor_sync(0xffffffffu, p2, 16);

        float a = (p1 + q1) + (p2 + q2);
        float hn = tanh_fast(a);

        // Masked recurrence: token 0 carries previous state (block-uniform).
        if (tok0 != 0) h = hn;
        s += h;

        // Publish into the other buffer (one writer per output).
        if (low) hbuf[(t & 1) ^ 1][j] = h;
        __syncthreads();

        tok0 = tok1; tok1 = tok2; tok2 = tok3;
        ew0 = ew1;  ew1 = ew2;
    }

    // Epilogue: mean pool -> dense (64 -> 2) -> sigmoid. Output j is held by
    // 2 lanes; count only l<16.
    float p  = s * (1.0f / NT);
    float c0 = low ? p * Wd[j * NC + 0] : 0.f;
    float c1 = low ? p * Wd[j * NC + 1] : 0.f;
    #pragma unroll
    for (int off = 16; off; off >>= 1) {
        c0 += __shfl_xor_sync(0xffffffffu, c0, off);
        c1 += __shfl_xor_sync(0xffffffffu, c1, off);
    }
    if (l == 0) { red[w][0] = c0; red[w][1] = c1; }
    __syncthreads();
    if (threadIdx.x == 0) {
        float C0 = red[0][0] + red[1][0] + red[2][0] + red[3][0] + bd[0];
        float C1 = red[0][1] + red[1][1] + red[2][1] + red[3][1] + bd[1];
        out[b * NC + 0] = 1.0f / (1.0f + expf(-C0));
        out[b * NC + 1] = 1.0f / (1.0f + expf(-C1));
    }
}

// ---------------------------------------------------------------------------
extern "C" void kernel_launch(void* const* d_in, const int* in_sizes, int n_in,
                              void* d_out, int out_size) {
    const int*   tokens = (const int*)  d_in[0];
    const float* E      = (const float*)d_in[1];
    const float* W      = (const float*)d_in[2];
    const float* U      = (const float*)d_in[3];
    const float* bias   = (const float*)d_in[4];
    const float* Wd     = (const float*)d_in[5];
    const float* bd     = (const float*)d_in[6];
    float* out = (float*)d_out;

    ew_kernel<<<(NV + 3) / 4, 256>>>(E, W, bias);
    rnn_kernel<<<NB, 128>>>(tokens, U, Wd, bd, out);
}